// round 5
// baseline (speedup 1.0000x reference)
#include <cuda_runtime.h>
#include <math.h>

// Problem constants
#define NROWS   16384        // 8*2048
#define DIM     64
#define NEMB    8192
#define TOPK    10
#define SPLITK  8
#define KPART   (NEMB / SPLITK)   // 1024
#define TILE    128
#define NTILES  (KPART / TILE)    // 8

// Output layout (float32 concat of tuple in return order)
#define OFF_Q     0
#define OFF_LOSS  (NROWS * DIM)                 // 1048576
#define OFF_IDX   (OFF_LOSS + 1)                // 1048577
#define OFF_MIND  (OFF_IDX + NROWS)             // 1064961
#define OFF_PERP  (OFF_MIND + NROWS)            // 1081345

typedef unsigned long long ull;

// ---- packed fp32x2 helpers (PTX only; ptxas won't auto-fuse) ----
__device__ __forceinline__ ull fma2(ull a, ull b, ull c) {
    ull d;
    asm("fma.rn.f32x2 %0, %1, %2, %3;" : "=l"(d) : "l"(a), "l"(b), "l"(c));
    return d;
}
__device__ __forceinline__ ull add2(ull a, ull b) {
    ull d;
    asm("add.rn.f32x2 %0, %1, %2;" : "=l"(d) : "l"(a), "l"(b));
    return d;
}
__device__ __forceinline__ float lo2(ull a) { return __uint_as_float((unsigned)a); }
__device__ __forceinline__ float hi2(ull a) { return __uint_as_float((unsigned)(a >> 32)); }

// ---- scratch (static device arrays: no allocation allowed) ----
// top-k layout: [row][part][slot]  -> contiguous 80 floats per row for the merge
__device__ float g_topd[NROWS * SPLITK * TOPK];
__device__ int   g_topi[NROWS * SPLITK * TOPK];
__device__ float g_enorm[NEMB];
__device__ float g_xn[NROWS];
__device__ int   g_counts[NEMB];
__device__ float g_rowloss[NROWS];
__device__ int   g_selbi[NROWS];
__device__ int   g_selv[NROWS];

// ============================================================
// Phase 0: codebook norms + zero counts (re-zeroed every call:
// required for deterministic graph replay)
// ============================================================
__global__ void k_prep(const float* __restrict__ cb) {
    int i = blockIdx.x * blockDim.x + threadIdx.x;
    if (i < NEMB) {
        const float4* r = reinterpret_cast<const float4*>(cb + i * DIM);
        float s = 0.f;
#pragma unroll
        for (int j = 0; j < DIM / 4; j++) {
            float4 v = r[j];
            s += v.x * v.x + v.y * v.y + v.z * v.z + v.w * v.w;
        }
        g_enorm[i] = s;
        g_counts[i] = 0;
    }
}

// ============================================================
// Phase 1: distances + per-(row, kpart) sorted top-10
// grid = SPLITK * 128 blocks, 128 threads; thread = one row
// ulonglong2 = 16 B = 4 floats -> 64-float row = DIM/4 = 16 ulonglong2
// (each .x/.y is one packed f32x2 pair).
// ============================================================
__global__ void __launch_bounds__(128, 4)
k_dist(const float* __restrict__ inputs, const float* __restrict__ cb) {
    __shared__ ulonglong2 sh_e[TILE * (DIM / 4)];  // 128 rows * 256 B = 32 KB
    __shared__ float      sh_en[TILE];

    const int kpart  = blockIdx.x >> 7;         // 0..SPLITK-1
    const int rowblk = blockIdx.x & 127;
    const int row    = rowblk * 128 + threadIdx.x;

    // row in registers, packed as f32x2 pairs (16 x ulonglong2 = 64 floats)
    ulonglong2 x4[DIM / 4];
    const ulonglong2* xp = reinterpret_cast<const ulonglong2*>(inputs + (size_t)row * DIM);
#pragma unroll
    for (int j = 0; j < DIM / 4; j++) x4[j] = xp[j];

    // ||x||^2
    ull a0 = 0ull, a1 = 0ull;
#pragma unroll
    for (int j = 0; j < DIM / 4; j++) {
        a0 = fma2(x4[j].x, x4[j].x, a0);
        a1 = fma2(x4[j].y, x4[j].y, a1);
    }
    a0 = add2(a0, a1);
    const float xn = lo2(a0) + hi2(a0);
    if (kpart == 0) g_xn[row] = xn;

    float topd[TOPK];
    int   topi[TOPK];
#pragma unroll
    for (int j = 0; j < TOPK; j++) { topd[j] = 3.402823466e38f; topi[j] = 0; }

    const int kbase = kpart * KPART;

    for (int t = 0; t < NTILES; t++) {
        const int cb0 = kbase + t * TILE;
        __syncthreads();   // protect previous tile's readers before overwrite
        // load tile (coalesced float4 copy, layout identical to global)
        const float4* src = reinterpret_cast<const float4*>(cb + (size_t)cb0 * DIM);
        float4* dst = reinterpret_cast<float4*>(sh_e);
#pragma unroll
        for (int j = 0; j < (TILE * DIM / 4) / 128; j++)      // 16 float4 per thread
            dst[threadIdx.x + j * 128] = src[threadIdx.x + j * 128];
        sh_en[threadIdx.x] = g_enorm[cb0 + threadIdx.x];
        __syncthreads();

        const ulonglong2* ep = sh_e;
        for (int c = 0; c < TILE; c++) {
            ull b0 = 0ull, b1 = 0ull, b2 = 0ull, b3 = 0ull;
#pragma unroll
            for (int j = 0; j < DIM / 4; j += 2) {            // 8 iters
                ulonglong2 e0 = ep[j];
                ulonglong2 e1 = ep[j + 1];
                b0 = fma2(x4[j].x,     e0.x, b0);
                b1 = fma2(x4[j].y,     e0.y, b1);
                b2 = fma2(x4[j + 1].x, e1.x, b2);
                b3 = fma2(x4[j + 1].y, e1.y, b3);
            }
            ull s0 = add2(b0, b2);
            ull s1 = add2(b1, b3);
            ull s  = add2(s0, s1);
            float dot  = lo2(s) + hi2(s);
            // matches JAX rounding shape: (||x||^2 + ||e||^2) - 2*dot (2*dot exact)
            float dist = fmaf(-2.f, dot, xn + sh_en[c]);

            if (dist < topd[TOPK - 1]) {
                topd[TOPK - 1] = dist;
                topi[TOPK - 1] = cb0 + c;
#pragma unroll
                for (int j = TOPK - 1; j > 0; --j) {
                    if (topd[j] < topd[j - 1]) {   // strict: stable for index ties
                        float td = topd[j]; topd[j] = topd[j - 1]; topd[j - 1] = td;
                        int   ti = topi[j]; topi[j] = topi[j - 1]; topi[j - 1] = ti;
                    }
                }
            }
            ep += DIM / 4;
        }
    }

    // row-major layout: [row][part][slot] -> contiguous merge reads
    const int o = (row * SPLITK + kpart) * TOPK;
#pragma unroll
    for (int j = 0; j < TOPK; j++) {
        g_topd[o + j] = topd[j];
        g_topi[o + j] = topi[j];
    }
}

// ============================================================
// Phase 2a: 8-way stable merge -> global top-10 -> Gumbel-max
//           select -> idx / min_d outputs + counts
// ============================================================
__global__ void k_select(const float* __restrict__ gumbel,
                         float* __restrict__ out) {
    int row = blockIdx.x * blockDim.x + threadIdx.x;
    if (row >= NROWS) return;

    const float* td = g_topd + (size_t)row * SPLITK * TOPK;
    const int*   ti = g_topi + (size_t)row * SPLITK * TOPK;

    int pos[SPLITK];
#pragma unroll
    for (int p = 0; p < SPLITK; p++) pos[p] = 0;

    float bests = -3.402823466e38f;
    int   bi = 0;
    float bd = 0.f;

#pragma unroll
    for (int s = 0; s < TOPK; s++) {
        float md = 3.402823466e38f;
        int mp = 0, mpos = 0;
#pragma unroll
        for (int p = 0; p < SPLITK; p++) {
            int pp = pos[p];
            float v = (pp < TOPK) ? td[p * TOPK + pp] : 3.402823466e38f;
            if (v < md) { md = v; mp = p; mpos = pp; }  // strict: ties -> lower part = lower idx
        }
        int id = ti[mp * TOPK + mpos];
#pragma unroll
        for (int p = 0; p < SPLITK; p++) if (p == mp) pos[p]++;

        float sc = gumbel[row * TOPK + s] - md;   // logits = -d/TEMP, TEMP=1
        if (sc > bests) { bests = sc; bi = id; bd = md; }  // strict: argmax first-index
    }

    // validity: ||x|| > 1e-6  <=>  ||x||^2 > 1e-12
    bool valid = g_xn[row] > 1e-12f;

    out[OFF_IDX + row]  = (float)(valid ? bi : 0);
    out[OFF_MIND + row] = valid ? bd : 0.f;
    g_selbi[row] = bi;
    g_selv[row]  = valid ? 1 : 0;
    if (valid) atomicAdd(&g_counts[bi], 1);   // unmasked idx, gated add: matches .at[idx].add(valid)
}

// ============================================================
// Phase 2b: coalesced gather + quantized_st + per-row loss
// 16 threads (float4 lanes) per row, 256 threads/block = 16 rows
// ============================================================
__global__ void k_gather(const float* __restrict__ inputs,
                         const float* __restrict__ cb,
                         float* __restrict__ out) {
    const int t    = blockIdx.x * blockDim.x + threadIdx.x;
    const int row  = t >> 4;
    const int lane = t & 15;

    const int bi    = g_selbi[row];
    const int valid = g_selv[row];

    float4 xv = reinterpret_cast<const float4*>(inputs + (size_t)row * DIM)[lane];
    float4 qv = make_float4(0.f, 0.f, 0.f, 0.f);
    if (valid) qv = reinterpret_cast<const float4*>(cb + (size_t)bi * DIM)[lane];

    // quantized_st = x + (q_masked - x)  (replicates reference fp ops exactly,
    // incl. invalid rows: x + (0 - x) == 0)
    float4 st;
    float dx = qv.x - xv.x, dy = qv.y - xv.y, dz = qv.z - xv.z, dw = qv.w - xv.w;
    st.x = xv.x + dx; st.y = xv.y + dy; st.z = xv.z + dz; st.w = xv.w + dw;
    reinterpret_cast<float4*>(out + OFF_Q + (size_t)row * DIM)[lane] = st;

    float lsum = valid ? (dx * dx + dy * dy + dz * dz + dw * dw) : 0.f;
#pragma unroll
    for (int o = 8; o > 0; o >>= 1)
        lsum += __shfl_down_sync(0xffffffffu, lsum, o, 16);
    if (lane == 0) g_rowloss[row] = lsum;
}

// ============================================================
// Phase 3: deterministic reductions -> total_loss, perplexity
// ============================================================
__global__ void k_finalize(float* __restrict__ out) {
    __shared__ float sf[1024];
    const int t = threadIdx.x;

    // n_valid = sum(counts)  (exact: integers < 2^24)
    int cs = 0;
    for (int i = t; i < NEMB; i += 1024) cs += g_counts[i];
    sf[t] = (float)cs;
    __syncthreads();
    for (int s = 512; s > 0; s >>= 1) { if (t < s) sf[t] += sf[t + s]; __syncthreads(); }
    float nv = fmaxf(sf[0], 1.0f);
    __syncthreads();

    // S = sum p*log(p + 1e-10)
    float es = 0.f;
    for (int i = t; i < NEMB; i += 1024) {
        float p = (float)g_counts[i] / nv;
        es += p * logf(p + 1e-10f);
    }
    sf[t] = es;
    __syncthreads();
    for (int s = 512; s > 0; s >>= 1) { if (t < s) sf[t] += sf[t + s]; __syncthreads(); }
    float S = sf[0];
    __syncthreads();

    // loss sum
    float ls = 0.f;
    for (int i = t; i < NROWS; i += 1024) ls += g_rowloss[i];
    sf[t] = ls;
    __syncthreads();
    for (int s = 512; s > 0; s >>= 1) { if (t < s) sf[t] += sf[t + s]; __syncthreads(); }

    if (t == 0) {
        float loss_vq = sf[0] / (nv * (float)DIM);
        float perp    = expf(-S);
        float ploss   = -logf(perp + 1e-10f);
        out[OFF_LOSS] = loss_vq + 0.01f * ploss;
        out[OFF_PERP] = perp;
    }
}

// ============================================================
extern "C" void kernel_launch(void* const* d_in, const int* in_sizes, int n_in,
                              void* d_out, int out_size) {
    const float* inputs = nullptr;
    const float* codebook = nullptr;
    const float* gumbel = nullptr;
    for (int i = 0; i < n_in; i++) {
        int s = in_sizes[i];
        if (s == NROWS * DIM)       inputs   = (const float*)d_in[i];
        else if (s == NEMB * DIM)   codebook = (const float*)d_in[i];
        else if (s == NROWS * TOPK) gumbel   = (const float*)d_in[i];
    }
    float* out = (float*)d_out;

    k_prep<<<(NEMB + 255) / 256, 256>>>(codebook);
    k_dist<<<SPLITK * 128, 128>>>(inputs, codebook);
    k_select<<<NROWS / 256, 256>>>(gumbel, out);
    k_gather<<<(NROWS * 16) / 256, 256>>>(inputs, codebook, out);
    k_finalize<<<1, 1024>>>(out);
}